// round 14
// baseline (speedup 1.0000x reference)
#include <cuda_runtime.h>
#include <cstdint>

#define N0 4096
#define N1 8192
#define N2 4096
#define NBLK 296           // 2 CTAs per SM
#define BLK 512

// Scratch (allocation-free: __device__ global)
__device__ __align__(16) float g_x1[N1];

__device__ __forceinline__ float warp_sum(float v) {
#pragma unroll
    for (int o = 16; o > 0; o >>= 1) v += __shfl_xor_sync(0xffffffffu, v, o);
    return v;
}

__device__ __forceinline__ uint32_t smem_u32(const void* p) {
    return (uint32_t)__cvta_generic_to_shared(p);
}
__device__ __forceinline__ void cp_async16(uint32_t dst, const void* src) {
    asm volatile("cp.async.cg.shared.global [%0], [%1], 16;" :: "r"(dst), "l"(src));
}
#define CP_COMMIT() asm volatile("cp.async.commit_group;" ::: "memory")
#define CP_WAIT(n)  asm volatile("cp.async.wait_group %0;" :: "n"(n) : "memory")

// Block-wide reduction of 8 partial sums (512 threads / 16 warps). Deterministic.
__device__ __forceinline__ void block_reduce8(float s[8], float (*sh)[16], float* s_sums)
{
    int tid = threadIdx.x;
    int w = tid >> 5, l = tid & 31;
#pragma unroll
    for (int k = 0; k < 8; k++) s[k] = warp_sum(s[k]);
    if (l == 0) {
#pragma unroll
        for (int k = 0; k < 8; k++) sh[k][w] = s[k];
    }
    __syncthreads();
    if (tid < 256) {
        int k = tid >> 5, ln = tid & 31;
        float v = (ln < 16) ? sh[k][ln] : 0.f;
        v = warp_sum(v);
        if (ln == 0) s_sums[k] = v;
    }
}

__device__ __forceinline__ float heb_row_val(
    int row,
    const float* __restrict__ act_post,
    const float* __restrict__ b_post,
    const float* __restrict__ c_post,
    const float* __restrict__ d_post,
    const float* __restrict__ e_post,
    const float* __restrict__ sums)
{
    float P = b_post[row] * act_post[row];
    float C = c_post[row] * act_post[row];
    float D = d_post[row];
    float E = e_post[row];
    return 0.5f * (sums[0] + P * sums[1] + C * sums[2] + D * sums[3]
          + E * (sums[4] + P * sums[5] + C * sums[6] + D * sums[7]));
}

__device__ __forceinline__ void heb_partial4(
    float s[8], float4 xv, float4 actv, float4 av, float4 cv, float4 dv, float4 ev)
{
    float xs[4]  = {xv.x, xv.y, xv.z, xv.w};
    float acs[4] = {actv.x, actv.y, actv.z, actv.w};
    float as[4]  = {av.x, av.y, av.z, av.w};
    float cs[4]  = {cv.x, cv.y, cv.z, cv.w};
    float ds[4]  = {dv.x, dv.y, dv.z, dv.w};
    float es[4]  = {ev.x, ev.y, ev.z, ev.w};
#pragma unroll
    for (int j = 0; j < 4; j++) {
        float x = xs[j], e = es[j];
        float p = as[j] * acs[j];
        float c = cs[j] * acs[j];
        float d = ds[j];
        s[0] += e * p * x;  s[1] += e * x;
        s[2] += e * c * x;  s[3] += e * d * x;
        s[4] += p * x;      s[5] += x;
        s[6] += c * x;      s[7] += d * x;
    }
}

// ---------------------------------------------------------------------------
// Fused GEMV (R8 architecture): cp.async row pipeline NBUF deep, x in
// registers, thread t owns f4-columns {t, t+512, ...}. Per-row shfl reduce;
// no block barrier on the data path. Refill issued right after the FMAs
// (before the shfl tree) — register dep on wv proves the LDS completed.
// ---------------------------------------------------------------------------
template <int NCOL4, int NROWS_OUT, bool TANH_IN, bool TANH_OUT, int NBUF>
__device__ __forceinline__ void gemv_fused(
    const float* __restrict__ W,
    const float* __restrict__ xin_src,
    const float* __restrict__ act_pre,
    const float* __restrict__ a_pre,
    const float* __restrict__ c_pre,
    const float* __restrict__ d_pre,
    const float* __restrict__ e_pre,
    const float* __restrict__ act_post,
    const float* __restrict__ b_post,
    const float* __restrict__ c_post,
    const float* __restrict__ d_post,
    const float* __restrict__ e_post,
    float* __restrict__ out)
{
    constexpr int F4PT = NCOL4 / BLK;     // float4 per thread per row (2 or 4)

    extern __shared__ float4 dynbuf[];    // NBUF * NCOL4 float4 (96 KB)
    __shared__ float sh[8][16];
    __shared__ float s_sums[8];
    __shared__ float s_heb[32];
    __shared__ float s_part[2][8][16];

    int tid = threadIdx.x;
    int lane = tid & 31;
    int warp = tid >> 5;

    int r_lo = (int)(((long long)blockIdx.x * NROWS_OUT) / NBLK);
    int r_hi = (int)(((long long)(blockIdx.x + 1) * NROWS_OUT) / NBLK);
    int nrows = r_hi - r_lo;

    const float4* Wb = reinterpret_cast<const float4*>(W) + (size_t)r_lo * NCOL4;
    uint32_t sbase = smem_u32(dynbuf);

    // Kick off DRAM immediately: prefetch first NBUF rows.
#pragma unroll
    for (int r = 0; r < NBUF; r++) {
        if (r < nrows) {
#pragma unroll
            for (int j = 0; j < F4PT; j++) {
                int col = tid + j * BLK;
                cp_async16(sbase + (uint32_t)(r * NCOL4 + col) * 16u,
                           Wb + (size_t)r * NCOL4 + col);
            }
        }
        CP_COMMIT();
    }

    // x into registers (+tanh), Hebbian pre-side sums (overlaps prefetch).
    float4 xr[F4PT];
    {
        float s[8] = {0.f, 0.f, 0.f, 0.f, 0.f, 0.f, 0.f, 0.f};
#pragma unroll
        for (int j = 0; j < F4PT; j++) {
            int i = tid + j * BLK;
            float4 xv = reinterpret_cast<const float4*>(xin_src)[i];
            if (TANH_IN)
                xv = make_float4(tanhf(xv.x), tanhf(xv.y), tanhf(xv.z), tanhf(xv.w));
            xr[j] = xv;
            float4 actv = reinterpret_cast<const float4*>(act_pre)[i];
            float4 av   = reinterpret_cast<const float4*>(a_pre)[i];
            float4 cv   = reinterpret_cast<const float4*>(c_pre)[i];
            float4 dv   = reinterpret_cast<const float4*>(d_pre)[i];
            float4 ev   = reinterpret_cast<const float4*>(e_pre)[i];
            heb_partial4(s, xv, actv, av, cv, dv, ev);
        }
        block_reduce8(s, sh, s_sums);
    }
    __syncthreads();
    if (tid < nrows) {
        s_heb[tid] = heb_row_val(r_lo + tid, act_post, b_post, c_post, d_post,
                                 e_post, s_sums);
    }
    __syncthreads();

    // Rolling state.
    int rdSlot = 0;
    int wrSlot = 0;                               // row NBUF writes slot 0
    const float4* gsrc = Wb + (size_t)NBUF * NCOL4 + tid;

    int par = 0;
    for (int r = 0; r < nrows; r++) {
        CP_WAIT(NBUF - 1);

        const float4* buf = dynbuf + (size_t)rdSlot * NCOL4;
        float4 wv[F4PT];
#pragma unroll
        for (int j = 0; j < F4PT; j++) wv[j] = buf[tid + j * BLK];
        rdSlot = (rdSlot + 1 == NBUF) ? 0 : rdSlot + 1;

        float acc = 0.f;
#pragma unroll
        for (int j = 0; j < F4PT; j++) {
            acc = fmaf(wv[j].x, xr[j].x, acc);
            acc = fmaf(wv[j].y, xr[j].y, acc);
            acc = fmaf(wv[j].z, xr[j].z, acc);
            acc = fmaf(wv[j].w, xr[j].w, acc);
        }

        // Refill issued here (before the shfl tree): the FMAs above consumed
        // wv, proving the LDS of this slot completed -> no WAR hazard.
        if (r + NBUF < nrows) {
            uint32_t wbase = sbase + (uint32_t)(wrSlot * NCOL4 + tid) * 16u;
#pragma unroll
            for (int j = 0; j < F4PT; j++)
                cp_async16(wbase + (uint32_t)(j * BLK) * 16u, gsrc + j * BLK);
        }
        wrSlot = (wrSlot + 1 == NBUF) ? 0 : wrSlot + 1;
        gsrc += NCOL4;
        CP_COMMIT();

        float p = warp_sum(acc);
        if (lane == 0) s_part[par][r & 7][warp] = p;

        if ((r & 7) == 7 || r == nrows - 1) {
            __syncthreads();
            if (tid < 256) {
                int rr = (r & ~7) + warp;     // warp = 0..7 here
                if (rr < nrows) {
                    float v = (lane < 16) ? s_part[par][warp][lane] : 0.f;
                    v = warp_sum(v);
                    if (lane == 0) {
                        float y = v + s_heb[rr];
                        out[r_lo + rr] = TANH_OUT ? tanhf(y) : y;
                    }
                }
            }
            par ^= 1;
        }
    }
}

// ---------------------------------------------------------------------------
__global__ void __launch_bounds__(BLK, 2) k_gemv0(
    const float* __restrict__ W0,
    const float* __restrict__ inputs,
    const float* __restrict__ act0,
    const float* __restrict__ a0,
    const float* __restrict__ c0,
    const float* __restrict__ d0,
    const float* __restrict__ e0,
    const float* __restrict__ act1,
    const float* __restrict__ b1,
    const float* __restrict__ c1,
    const float* __restrict__ d1,
    const float* __restrict__ e1)
{
    gemv_fused<N0 / 4, N1, true, true, 6>(
        W0, inputs, act0, a0, c0, d0, e0,
        act1, b1, c1, d1, e1, g_x1);
}

__global__ void __launch_bounds__(BLK, 2) k_gemv1(
    const float* __restrict__ W1,
    const float* __restrict__ act1,
    const float* __restrict__ a1,
    const float* __restrict__ c1,
    const float* __restrict__ d1,
    const float* __restrict__ e1,
    const float* __restrict__ act2,
    const float* __restrict__ b2,
    const float* __restrict__ c2,
    const float* __restrict__ d2,
    const float* __restrict__ e2,
    float* __restrict__ out)
{
    gemv_fused<N1 / 4, N2, false, false, 3>(
        W1, g_x1, act1, a1, c1, d1, e1,
        act2, b2, c2, d2, e2, out);
}

// ---------------------------------------------------------------------------
extern "C" void kernel_launch(void* const* d_in, const int* in_sizes, int n_in,
                              void* d_out, int out_size)
{
    const float* inputs = (const float*)d_in[0];
    const float* act0   = (const float*)d_in[1];
    const float* act1   = (const float*)d_in[2];
    const float* act2   = (const float*)d_in[3];
    const float* W0     = (const float*)d_in[4];
    const float* W1     = (const float*)d_in[5];
    const float* a0     = (const float*)d_in[6];
    const float* c0     = (const float*)d_in[7];
    const float* d0     = (const float*)d_in[8];
    const float* e0     = (const float*)d_in[9];
    const float* a1     = (const float*)d_in[10];
    const float* b1     = (const float*)d_in[11];
    const float* c1     = (const float*)d_in[12];
    const float* d1     = (const float*)d_in[13];
    const float* e1     = (const float*)d_in[14];
    const float* b2     = (const float*)d_in[15];
    const float* c2     = (const float*)d_in[16];
    const float* d2     = (const float*)d_in[17];
    const float* e2     = (const float*)d_in[18];
    float* out = (float*)d_out;

    // 6 buffers * 1024 f4 (gemv0) == 3 buffers * 2048 f4 (gemv1) == 96 KB.
    const int SMEM_DYN = 6 * (N0 / 4) * (int)sizeof(float4);
    cudaFuncSetAttribute(k_gemv0, cudaFuncAttributeMaxDynamicSharedMemorySize, SMEM_DYN);
    cudaFuncSetAttribute(k_gemv1, cudaFuncAttributeMaxDynamicSharedMemorySize, SMEM_DYN);

    k_gemv0<<<NBLK, BLK, SMEM_DYN>>>(W0, inputs, act0, a0, c0, d0, e0,
                                     act1, b1, c1, d1, e1);
    k_gemv1<<<NBLK, BLK, SMEM_DYN>>>(W1, act1, a1, c1, d1, e1,
                                     act2, b2, c2, d2, e2, out);
}

// round 15
// speedup vs baseline: 1.0167x; 1.0167x over previous
#include <cuda_runtime.h>
#include <cstdint>

#define N0 4096
#define N1 8192
#define N2 4096
#define NBLK 296           // 2 CTAs per SM
#define BLK 512

// Scratch (allocation-free: __device__ global)
__device__ __align__(16) float g_x1[N1];

__device__ __forceinline__ float warp_sum(float v) {
#pragma unroll
    for (int o = 16; o > 0; o >>= 1) v += __shfl_xor_sync(0xffffffffu, v, o);
    return v;
}

__device__ __forceinline__ uint32_t smem_u32(const void* p) {
    return (uint32_t)__cvta_generic_to_shared(p);
}
__device__ __forceinline__ void cp_async16(uint32_t dst, const void* src) {
    asm volatile("cp.async.cg.shared.global [%0], [%1], 16;" :: "r"(dst), "l"(src));
}
#define CP_COMMIT() asm volatile("cp.async.commit_group;" ::: "memory")
#define CP_WAIT(n)  asm volatile("cp.async.wait_group %0;" :: "n"(n) : "memory")

// PDL controls (sm_90+)
__device__ __forceinline__ void pdl_trigger() {
    asm volatile("griddepcontrol.launch_dependents;" ::: "memory");
}
__device__ __forceinline__ void pdl_wait() {
    asm volatile("griddepcontrol.wait;" ::: "memory");
}

// Block-wide reduction of 8 partial sums (512 threads / 16 warps). Deterministic.
__device__ __forceinline__ void block_reduce8(float s[8], float (*sh)[16], float* s_sums)
{
    int tid = threadIdx.x;
    int w = tid >> 5, l = tid & 31;
#pragma unroll
    for (int k = 0; k < 8; k++) s[k] = warp_sum(s[k]);
    if (l == 0) {
#pragma unroll
        for (int k = 0; k < 8; k++) sh[k][w] = s[k];
    }
    __syncthreads();
    if (tid < 256) {
        int k = tid >> 5, ln = tid & 31;
        float v = (ln < 16) ? sh[k][ln] : 0.f;
        v = warp_sum(v);
        if (ln == 0) s_sums[k] = v;
    }
}

__device__ __forceinline__ float heb_row_val(
    int row,
    const float* __restrict__ act_post,
    const float* __restrict__ b_post,
    const float* __restrict__ c_post,
    const float* __restrict__ d_post,
    const float* __restrict__ e_post,
    const float* __restrict__ sums)
{
    float P = b_post[row] * act_post[row];
    float C = c_post[row] * act_post[row];
    float D = d_post[row];
    float E = e_post[row];
    return 0.5f * (sums[0] + P * sums[1] + C * sums[2] + D * sums[3]
          + E * (sums[4] + P * sums[5] + C * sums[6] + D * sums[7]));
}

__device__ __forceinline__ void heb_partial4(
    float s[8], float4 xv, float4 actv, float4 av, float4 cv, float4 dv, float4 ev)
{
    float xs[4]  = {xv.x, xv.y, xv.z, xv.w};
    float acs[4] = {actv.x, actv.y, actv.z, actv.w};
    float as[4]  = {av.x, av.y, av.z, av.w};
    float cs[4]  = {cv.x, cv.y, cv.z, cv.w};
    float ds[4]  = {dv.x, dv.y, dv.z, dv.w};
    float es[4]  = {ev.x, ev.y, ev.z, ev.w};
#pragma unroll
    for (int j = 0; j < 4; j++) {
        float x = xs[j], e = es[j];
        float p = as[j] * acs[j];
        float c = cs[j] * acs[j];
        float d = ds[j];
        s[0] += e * p * x;  s[1] += e * x;
        s[2] += e * c * x;  s[3] += e * d * x;
        s[4] += p * x;      s[5] += x;
        s[6] += c * x;      s[7] += d * x;
    }
}

// ---------------------------------------------------------------------------
// Fused GEMV (R8 architecture): cp.async row pipeline NBUF deep, x in
// registers, thread t owns f4-columns {t, t+512, ...}. Per-row shfl reduce;
// no block barrier on the data path.
// PDL_TRIG: signal dependents launchable after our prologue prefetch.
// PDL_WAIT: wait for prior grid's memory (g_x1) before the x staging phase.
// ---------------------------------------------------------------------------
template <int NCOL4, int NROWS_OUT, bool TANH_IN, bool TANH_OUT, int NBUF,
          bool PDL_TRIG, bool PDL_WAIT>
__device__ __forceinline__ void gemv_fused(
    const float* __restrict__ W,
    const float* __restrict__ xin_src,
    const float* __restrict__ act_pre,
    const float* __restrict__ a_pre,
    const float* __restrict__ c_pre,
    const float* __restrict__ d_pre,
    const float* __restrict__ e_pre,
    const float* __restrict__ act_post,
    const float* __restrict__ b_post,
    const float* __restrict__ c_post,
    const float* __restrict__ d_post,
    const float* __restrict__ e_post,
    float* __restrict__ out)
{
    constexpr int F4PT = NCOL4 / BLK;     // float4 per thread per row (2 or 4)

    extern __shared__ float4 dynbuf[];    // NBUF * NCOL4 float4 (96 KB)
    __shared__ float sh[8][16];
    __shared__ float s_sums[8];
    __shared__ float s_heb[32];
    __shared__ float s_part[2][8][16];

    int tid = threadIdx.x;
    int lane = tid & 31;
    int warp = tid >> 5;

    int r_lo = (int)(((long long)blockIdx.x * NROWS_OUT) / NBLK);
    int r_hi = (int)(((long long)(blockIdx.x + 1) * NROWS_OUT) / NBLK);
    int nrows = r_hi - r_lo;

    const float4* Wb = reinterpret_cast<const float4*>(W) + (size_t)r_lo * NCOL4;
    uint32_t sbase = smem_u32(dynbuf);

    // Kick off DRAM immediately: prefetch first NBUF rows (W only — input data,
    // safe before pdl_wait).
#pragma unroll
    for (int r = 0; r < NBUF; r++) {
        if (r < nrows) {
#pragma unroll
            for (int j = 0; j < F4PT; j++) {
                int col = tid + j * BLK;
                cp_async16(sbase + (uint32_t)(r * NCOL4 + col) * 16u,
                           Wb + (size_t)r * NCOL4 + col);
            }
        }
        CP_COMMIT();
    }

    if (PDL_TRIG) pdl_trigger();   // dependents may start launching now
    if (PDL_WAIT) pdl_wait();      // prior grid's writes (g_x1) now visible

    // x into registers (+tanh), Hebbian pre-side sums (overlaps prefetch).
    float4 xr[F4PT];
    {
        float s[8] = {0.f, 0.f, 0.f, 0.f, 0.f, 0.f, 0.f, 0.f};
#pragma unroll
        for (int j = 0; j < F4PT; j++) {
            int i = tid + j * BLK;
            float4 xv = reinterpret_cast<const float4*>(xin_src)[i];
            if (TANH_IN)
                xv = make_float4(tanhf(xv.x), tanhf(xv.y), tanhf(xv.z), tanhf(xv.w));
            xr[j] = xv;
            float4 actv = reinterpret_cast<const float4*>(act_pre)[i];
            float4 av   = reinterpret_cast<const float4*>(a_pre)[i];
            float4 cv   = reinterpret_cast<const float4*>(c_pre)[i];
            float4 dv   = reinterpret_cast<const float4*>(d_pre)[i];
            float4 ev   = reinterpret_cast<const float4*>(e_pre)[i];
            heb_partial4(s, xv, actv, av, cv, dv, ev);
        }
        block_reduce8(s, sh, s_sums);
    }
    __syncthreads();
    if (tid < nrows) {
        s_heb[tid] = heb_row_val(r_lo + tid, act_post, b_post, c_post, d_post,
                                 e_post, s_sums);
    }
    __syncthreads();

    // Rolling state.
    int rdSlot = 0;
    int wrSlot = 0;                               // row NBUF writes slot 0
    const float4* gsrc = Wb + (size_t)NBUF * NCOL4 + tid;

    int par = 0;
    for (int r = 0; r < nrows; r++) {
        CP_WAIT(NBUF - 1);

        const float4* buf = dynbuf + (size_t)rdSlot * NCOL4;
        float4 wv[F4PT];
#pragma unroll
        for (int j = 0; j < F4PT; j++) wv[j] = buf[tid + j * BLK];
        rdSlot = (rdSlot + 1 == NBUF) ? 0 : rdSlot + 1;

        float acc = 0.f;
#pragma unroll
        for (int j = 0; j < F4PT; j++) {
            acc = fmaf(wv[j].x, xr[j].x, acc);
            acc = fmaf(wv[j].y, xr[j].y, acc);
            acc = fmaf(wv[j].z, xr[j].z, acc);
            acc = fmaf(wv[j].w, xr[j].w, acc);
        }
        float p = warp_sum(acc);
        if (lane == 0) s_part[par][r & 7][warp] = p;

        if (r + NBUF < nrows) {
            uint32_t wbase = sbase + (uint32_t)(wrSlot * NCOL4 + tid) * 16u;
#pragma unroll
            for (int j = 0; j < F4PT; j++)
                cp_async16(wbase + (uint32_t)(j * BLK) * 16u, gsrc + j * BLK);
        }
        wrSlot = (wrSlot + 1 == NBUF) ? 0 : wrSlot + 1;
        gsrc += NCOL4;
        CP_COMMIT();

        if ((r & 7) == 7 || r == nrows - 1) {
            __syncthreads();
            if (tid < 256) {
                int rr = (r & ~7) + warp;     // warp = 0..7 here
                if (rr < nrows) {
                    float v = (lane < 16) ? s_part[par][warp][lane] : 0.f;
                    v = warp_sum(v);
                    if (lane == 0) {
                        float y = v + s_heb[rr];
                        out[r_lo + rr] = TANH_OUT ? tanhf(y) : y;
                    }
                }
            }
            par ^= 1;
        }
    }
}

// ---------------------------------------------------------------------------
__global__ void __launch_bounds__(BLK, 2) k_gemv0(
    const float* __restrict__ W0,
    const float* __restrict__ inputs,
    const float* __restrict__ act0,
    const float* __restrict__ a0,
    const float* __restrict__ c0,
    const float* __restrict__ d0,
    const float* __restrict__ e0,
    const float* __restrict__ act1,
    const float* __restrict__ b1,
    const float* __restrict__ c1,
    const float* __restrict__ d1,
    const float* __restrict__ e1)
{
    gemv_fused<N0 / 4, N1, true, true, 6, true, false>(
        W0, inputs, act0, a0, c0, d0, e0,
        act1, b1, c1, d1, e1, g_x1);
}

__global__ void __launch_bounds__(BLK, 2) k_gemv1(
    const float* __restrict__ W1,
    const float* __restrict__ act1,
    const float* __restrict__ a1,
    const float* __restrict__ c1,
    const float* __restrict__ d1,
    const float* __restrict__ e1,
    const float* __restrict__ act2,
    const float* __restrict__ b2,
    const float* __restrict__ c2,
    const float* __restrict__ d2,
    const float* __restrict__ e2,
    float* __restrict__ out)
{
    gemv_fused<N1 / 4, N2, false, false, 3, false, true>(
        W1, g_x1, act1, a1, c1, d1, e1,
        act2, b2, c2, d2, e2, out);
}

// ---------------------------------------------------------------------------
extern "C" void kernel_launch(void* const* d_in, const int* in_sizes, int n_in,
                              void* d_out, int out_size)
{
    const float* inputs = (const float*)d_in[0];
    const float* act0   = (const float*)d_in[1];
    const float* act1   = (const float*)d_in[2];
    const float* act2   = (const float*)d_in[3];
    const float* W0     = (const float*)d_in[4];
    const float* W1     = (const float*)d_in[5];
    const float* a0     = (const float*)d_in[6];
    const float* c0     = (const float*)d_in[7];
    const float* d0     = (const float*)d_in[8];
    const float* e0     = (const float*)d_in[9];
    const float* a1     = (const float*)d_in[10];
    const float* b1     = (const float*)d_in[11];
    const float* c1     = (const float*)d_in[12];
    const float* d1     = (const float*)d_in[13];
    const float* e1     = (const float*)d_in[14];
    const float* b2     = (const float*)d_in[15];
    const float* c2     = (const float*)d_in[16];
    const float* d2     = (const float*)d_in[17];
    const float* e2     = (const float*)d_in[18];
    float* out = (float*)d_out;

    // 6 buffers * 1024 f4 (gemv0) == 3 buffers * 2048 f4 (gemv1) == 96 KB.
    const int SMEM_DYN = 6 * (N0 / 4) * (int)sizeof(float4);
    static bool attr_done = false;
    if (!attr_done) {
        cudaFuncSetAttribute(k_gemv0, cudaFuncAttributeMaxDynamicSharedMemorySize, SMEM_DYN);
        cudaFuncSetAttribute(k_gemv1, cudaFuncAttributeMaxDynamicSharedMemorySize, SMEM_DYN);
        attr_done = true;
    }

    // Primary: normal launch.
    k_gemv0<<<NBLK, BLK, SMEM_DYN>>>(W0, inputs, act0, a0, c0, d0, e0,
                                     act1, b1, c1, d1, e1);

    // Secondary: programmatic dependent launch (overlaps its W1 prefetch with
    // gemv0's tail; pdl_wait() inside orders the g_x1 reads).
    cudaLaunchConfig_t cfg = {};
    cfg.gridDim = dim3(NBLK, 1, 1);
    cfg.blockDim = dim3(BLK, 1, 1);
    cfg.dynamicSmemBytes = (size_t)SMEM_DYN;
    cfg.stream = 0;
    cudaLaunchAttribute attrs[1];
    attrs[0].id = cudaLaunchAttributeProgrammaticStreamSerialization;
    attrs[0].val.programmaticStreamSerializationAllowed = 1;
    cfg.attrs = attrs;
    cfg.numAttrs = 1;
    cudaLaunchKernelEx(&cfg, k_gemv1,
                       W1, act1, a1, c1, d1, e1,
                       act2, b2, c2, d2, e2, out);
}

// round 16
// speedup vs baseline: 1.0209x; 1.0042x over previous
#include <cuda_runtime.h>
#include <cstdint>

#define N0 4096
#define N1 8192
#define N2 4096
#define NBLK 296           // 2 CTAs per SM
#define BLK 512

// Scratch (allocation-free: __device__ global)
__device__ __align__(16) float g_x1[N1];

__device__ __forceinline__ float warp_sum(float v) {
#pragma unroll
    for (int o = 16; o > 0; o >>= 1) v += __shfl_xor_sync(0xffffffffu, v, o);
    return v;
}

__device__ __forceinline__ uint32_t smem_u32(const void* p) {
    return (uint32_t)__cvta_generic_to_shared(p);
}
__device__ __forceinline__ void cp_async16(uint32_t dst, const void* src) {
    asm volatile("cp.async.cg.shared.global [%0], [%1], 16;" :: "r"(dst), "l"(src));
}
#define CP_COMMIT() asm volatile("cp.async.commit_group;" ::: "memory")
#define CP_WAIT(n)  asm volatile("cp.async.wait_group %0;" :: "n"(n) : "memory")

// PDL controls (sm_90+)
__device__ __forceinline__ void pdl_trigger() {
    asm volatile("griddepcontrol.launch_dependents;" ::: "memory");
}
__device__ __forceinline__ void pdl_wait() {
    asm volatile("griddepcontrol.wait;" ::: "memory");
}

// Block-wide reduction of 8 partial sums (512 threads / 16 warps). Deterministic.
__device__ __forceinline__ void block_reduce8(float s[8], float (*sh)[16], float* s_sums)
{
    int tid = threadIdx.x;
    int w = tid >> 5, l = tid & 31;
#pragma unroll
    for (int k = 0; k < 8; k++) s[k] = warp_sum(s[k]);
    if (l == 0) {
#pragma unroll
        for (int k = 0; k < 8; k++) sh[k][w] = s[k];
    }
    __syncthreads();
    if (tid < 256) {
        int k = tid >> 5, ln = tid & 31;
        float v = (ln < 16) ? sh[k][ln] : 0.f;
        v = warp_sum(v);
        if (ln == 0) s_sums[k] = v;
    }
}

__device__ __forceinline__ float heb_row_val(
    int row,
    const float* __restrict__ act_post,
    const float* __restrict__ b_post,
    const float* __restrict__ c_post,
    const float* __restrict__ d_post,
    const float* __restrict__ e_post,
    const float* __restrict__ sums)
{
    float P = b_post[row] * act_post[row];
    float C = c_post[row] * act_post[row];
    float D = d_post[row];
    float E = e_post[row];
    return 0.5f * (sums[0] + P * sums[1] + C * sums[2] + D * sums[3]
          + E * (sums[4] + P * sums[5] + C * sums[6] + D * sums[7]));
}

__device__ __forceinline__ void heb_partial4(
    float s[8], float4 xv, float4 actv, float4 av, float4 cv, float4 dv, float4 ev)
{
    float xs[4]  = {xv.x, xv.y, xv.z, xv.w};
    float acs[4] = {actv.x, actv.y, actv.z, actv.w};
    float as[4]  = {av.x, av.y, av.z, av.w};
    float cs[4]  = {cv.x, cv.y, cv.z, cv.w};
    float ds[4]  = {dv.x, dv.y, dv.z, dv.w};
    float es[4]  = {ev.x, ev.y, ev.z, ev.w};
#pragma unroll
    for (int j = 0; j < 4; j++) {
        float x = xs[j], e = es[j];
        float p = as[j] * acs[j];
        float c = cs[j] * acs[j];
        float d = ds[j];
        s[0] += e * p * x;  s[1] += e * x;
        s[2] += e * c * x;  s[3] += e * d * x;
        s[4] += p * x;      s[5] += x;
        s[6] += c * x;      s[7] += d * x;
    }
}

// ---------------------------------------------------------------------------
// Fused GEMV (R8 architecture): cp.async row pipeline NBUF deep, x in
// registers, thread t owns f4-columns {t, t+512, ...}. Per-row shfl reduce;
// no block barrier on the data path.
// PDL_TRIG: signal dependents launchable after our prologue prefetch.
// PDL_WAIT: wait for prior grid's memory (g_x1) before the x staging phase.
// ---------------------------------------------------------------------------
template <int NCOL4, int NROWS_OUT, bool TANH_IN, bool TANH_OUT, int NBUF,
          bool PDL_TRIG, bool PDL_WAIT>
__device__ __forceinline__ void gemv_fused(
    const float* __restrict__ W,
    const float* __restrict__ xin_src,
    const float* __restrict__ act_pre,
    const float* __restrict__ a_pre,
    const float* __restrict__ c_pre,
    const float* __restrict__ d_pre,
    const float* __restrict__ e_pre,
    const float* __restrict__ act_post,
    const float* __restrict__ b_post,
    const float* __restrict__ c_post,
    const float* __restrict__ d_post,
    const float* __restrict__ e_post,
    float* __restrict__ out)
{
    constexpr int F4PT = NCOL4 / BLK;     // float4 per thread per row (2 or 4)

    extern __shared__ float4 dynbuf[];    // NBUF * NCOL4 float4 (96 KB)
    __shared__ float sh[8][16];
    __shared__ float s_sums[8];
    __shared__ float s_heb[32];
    __shared__ float s_part[2][8][16];

    int tid = threadIdx.x;
    int lane = tid & 31;
    int warp = tid >> 5;

    int r_lo = (int)(((long long)blockIdx.x * NROWS_OUT) / NBLK);
    int r_hi = (int)(((long long)(blockIdx.x + 1) * NROWS_OUT) / NBLK);
    int nrows = r_hi - r_lo;

    const float4* Wb = reinterpret_cast<const float4*>(W) + (size_t)r_lo * NCOL4;
    uint32_t sbase = smem_u32(dynbuf);

    // Kick off DRAM immediately: prefetch first NBUF rows (W only — input data,
    // safe before pdl_wait).
#pragma unroll
    for (int r = 0; r < NBUF; r++) {
        if (r < nrows) {
#pragma unroll
            for (int j = 0; j < F4PT; j++) {
                int col = tid + j * BLK;
                cp_async16(sbase + (uint32_t)(r * NCOL4 + col) * 16u,
                           Wb + (size_t)r * NCOL4 + col);
            }
        }
        CP_COMMIT();
    }

    if (PDL_TRIG) pdl_trigger();   // dependents may start launching now
    if (PDL_WAIT) pdl_wait();      // prior grid's writes (g_x1) now visible

    // x into registers (+tanh), Hebbian pre-side sums (overlaps prefetch).
    float4 xr[F4PT];
    {
        float s[8] = {0.f, 0.f, 0.f, 0.f, 0.f, 0.f, 0.f, 0.f};
#pragma unroll
        for (int j = 0; j < F4PT; j++) {
            int i = tid + j * BLK;
            float4 xv = reinterpret_cast<const float4*>(xin_src)[i];
            if (TANH_IN)
                xv = make_float4(tanhf(xv.x), tanhf(xv.y), tanhf(xv.z), tanhf(xv.w));
            xr[j] = xv;
            float4 actv = reinterpret_cast<const float4*>(act_pre)[i];
            float4 av   = reinterpret_cast<const float4*>(a_pre)[i];
            float4 cv   = reinterpret_cast<const float4*>(c_pre)[i];
            float4 dv   = reinterpret_cast<const float4*>(d_pre)[i];
            float4 ev   = reinterpret_cast<const float4*>(e_pre)[i];
            heb_partial4(s, xv, actv, av, cv, dv, ev);
        }
        block_reduce8(s, sh, s_sums);
    }
    __syncthreads();
    if (tid < nrows) {
        s_heb[tid] = heb_row_val(r_lo + tid, act_post, b_post, c_post, d_post,
                                 e_post, s_sums);
    }
    __syncthreads();

    // Rolling state.
    int rdSlot = 0;
    int wrSlot = 0;                               // row NBUF writes slot 0
    const float4* gsrc = Wb + (size_t)NBUF * NCOL4 + tid;

    int par = 0;
    for (int r = 0; r < nrows; r++) {
        CP_WAIT(NBUF - 1);

        const float4* buf = dynbuf + (size_t)rdSlot * NCOL4;
        float4 wv[F4PT];
#pragma unroll
        for (int j = 0; j < F4PT; j++) wv[j] = buf[tid + j * BLK];
        rdSlot = (rdSlot + 1 == NBUF) ? 0 : rdSlot + 1;

        float acc = 0.f;
#pragma unroll
        for (int j = 0; j < F4PT; j++) {
            acc = fmaf(wv[j].x, xr[j].x, acc);
            acc = fmaf(wv[j].y, xr[j].y, acc);
            acc = fmaf(wv[j].z, xr[j].z, acc);
            acc = fmaf(wv[j].w, xr[j].w, acc);
        }
        float p = warp_sum(acc);
        if (lane == 0) s_part[par][r & 7][warp] = p;

        if (r + NBUF < nrows) {
            uint32_t wbase = sbase + (uint32_t)(wrSlot * NCOL4 + tid) * 16u;
#pragma unroll
            for (int j = 0; j < F4PT; j++)
                cp_async16(wbase + (uint32_t)(j * BLK) * 16u, gsrc + j * BLK);
        }
        wrSlot = (wrSlot + 1 == NBUF) ? 0 : wrSlot + 1;
        gsrc += NCOL4;
        CP_COMMIT();

        if ((r & 7) == 7 || r == nrows - 1) {
            __syncthreads();
            if (tid < 256) {
                int rr = (r & ~7) + warp;     // warp = 0..7 here
                if (rr < nrows) {
                    float v = (lane < 16) ? s_part[par][warp][lane] : 0.f;
                    v = warp_sum(v);
                    if (lane == 0) {
                        float y = v + s_heb[rr];
                        out[r_lo + rr] = TANH_OUT ? tanhf(y) : y;
                    }
                }
            }
            par ^= 1;
        }
    }
}

// ---------------------------------------------------------------------------
__global__ void __launch_bounds__(BLK, 2) k_gemv0(
    const float* __restrict__ W0,
    const float* __restrict__ inputs,
    const float* __restrict__ act0,
    const float* __restrict__ a0,
    const float* __restrict__ c0,
    const float* __restrict__ d0,
    const float* __restrict__ e0,
    const float* __restrict__ act1,
    const float* __restrict__ b1,
    const float* __restrict__ c1,
    const float* __restrict__ d1,
    const float* __restrict__ e1)
{
    gemv_fused<N0 / 4, N1, true, true, 6, true, false>(
        W0, inputs, act0, a0, c0, d0, e0,
        act1, b1, c1, d1, e1, g_x1);
}

__global__ void __launch_bounds__(BLK, 2) k_gemv1(
    const float* __restrict__ W1,
    const float* __restrict__ act1,
    const float* __restrict__ a1,
    const float* __restrict__ c1,
    const float* __restrict__ d1,
    const float* __restrict__ e1,
    const float* __restrict__ act2,
    const float* __restrict__ b2,
    const float* __restrict__ c2,
    const float* __restrict__ d2,
    const float* __restrict__ e2,
    float* __restrict__ out)
{
    gemv_fused<N1 / 4, N2, false, false, 3, false, true>(
        W1, g_x1, act1, a1, c1, d1, e1,
        act2, b2, c2, d2, e2, out);
}

// ---------------------------------------------------------------------------
extern "C" void kernel_launch(void* const* d_in, const int* in_sizes, int n_in,
                              void* d_out, int out_size)
{
    const float* inputs = (const float*)d_in[0];
    const float* act0   = (const float*)d_in[1];
    const float* act1   = (const float*)d_in[2];
    const float* act2   = (const float*)d_in[3];
    const float* W0     = (const float*)d_in[4];
    const float* W1     = (const float*)d_in[5];
    const float* a0     = (const float*)d_in[6];
    const float* c0     = (const float*)d_in[7];
    const float* d0     = (const float*)d_in[8];
    const float* e0     = (const float*)d_in[9];
    const float* a1     = (const float*)d_in[10];
    const float* b1     = (const float*)d_in[11];
    const float* c1     = (const float*)d_in[12];
    const float* d1     = (const float*)d_in[13];
    const float* e1     = (const float*)d_in[14];
    const float* b2     = (const float*)d_in[15];
    const float* c2     = (const float*)d_in[16];
    const float* d2     = (const float*)d_in[17];
    const float* e2     = (const float*)d_in[18];
    float* out = (float*)d_out;

    // 6 buffers * 1024 f4 (gemv0) == 3 buffers * 2048 f4 (gemv1) == 96 KB.
    const int SMEM_DYN = 6 * (N0 / 4) * (int)sizeof(float4);
    static bool attr_done = false;
    if (!attr_done) {
        cudaFuncSetAttribute(k_gemv0, cudaFuncAttributeMaxDynamicSharedMemorySize, SMEM_DYN);
        cudaFuncSetAttribute(k_gemv1, cudaFuncAttributeMaxDynamicSharedMemorySize, SMEM_DYN);
        attr_done = true;
    }

    // Primary: normal launch.
    k_gemv0<<<NBLK, BLK, SMEM_DYN>>>(W0, inputs, act0, a0, c0, d0, e0,
                                     act1, b1, c1, d1, e1);

    // Secondary: programmatic dependent launch (overlaps its W1 prefetch with
    // gemv0's tail; pdl_wait() inside orders the g_x1 reads).
    cudaLaunchConfig_t cfg = {};
    cfg.gridDim = dim3(NBLK, 1, 1);
    cfg.blockDim = dim3(BLK, 1, 1);
    cfg.dynamicSmemBytes = (size_t)SMEM_DYN;
    cfg.stream = 0;
    cudaLaunchAttribute attrs[1];
    attrs[0].id = cudaLaunchAttributeProgrammaticStreamSerialization;
    attrs[0].val.programmaticStreamSerializationAllowed = 1;
    cfg.attrs = attrs;
    cfg.numAttrs = 1;
    cudaLaunchKernelEx(&cfg, k_gemv1,
                       W1, act1, a1, c1, d1, e1,
                       act2, b2, c2, d2, e2, out);
}

// round 17
// speedup vs baseline: 1.0258x; 1.0048x over previous
#include <cuda_runtime.h>
#include <cstdint>

#define N0 4096
#define N1 8192
#define N2 4096
#define NBLK 296           // 2 CTAs per SM
#define BLK 512

// Scratch (allocation-free: __device__ global)
__device__ __align__(16) float g_x1[N1];

__device__ __forceinline__ float warp_sum(float v) {
#pragma unroll
    for (int o = 16; o > 0; o >>= 1) v += __shfl_xor_sync(0xffffffffu, v, o);
    return v;
}

__device__ __forceinline__ uint32_t smem_u32(const void* p) {
    return (uint32_t)__cvta_generic_to_shared(p);
}
__device__ __forceinline__ void cp_async16(uint32_t dst, const void* src) {
    asm volatile("cp.async.cg.shared.global [%0], [%1], 16;" :: "r"(dst), "l"(src));
}
#define CP_COMMIT() asm volatile("cp.async.commit_group;" ::: "memory")
#define CP_WAIT(n)  asm volatile("cp.async.wait_group %0;" :: "n"(n) : "memory")

// PDL controls (sm_90+)
__device__ __forceinline__ void pdl_trigger() {
    asm volatile("griddepcontrol.launch_dependents;" ::: "memory");
}
__device__ __forceinline__ void pdl_wait() {
    asm volatile("griddepcontrol.wait;" ::: "memory");
}

// Block-wide reduction of 8 partial sums (512 threads / 16 warps). Deterministic.
__device__ __forceinline__ void block_reduce8(float s[8], float (*sh)[16], float* s_sums)
{
    int tid = threadIdx.x;
    int w = tid >> 5, l = tid & 31;
#pragma unroll
    for (int k = 0; k < 8; k++) s[k] = warp_sum(s[k]);
    if (l == 0) {
#pragma unroll
        for (int k = 0; k < 8; k++) sh[k][w] = s[k];
    }
    __syncthreads();
    if (tid < 256) {
        int k = tid >> 5, ln = tid & 31;
        float v = (ln < 16) ? sh[k][ln] : 0.f;
        v = warp_sum(v);
        if (ln == 0) s_sums[k] = v;
    }
}

__device__ __forceinline__ float heb_row_val(
    int row,
    const float* __restrict__ act_post,
    const float* __restrict__ b_post,
    const float* __restrict__ c_post,
    const float* __restrict__ d_post,
    const float* __restrict__ e_post,
    const float* __restrict__ sums)
{
    float P = b_post[row] * act_post[row];
    float C = c_post[row] * act_post[row];
    float D = d_post[row];
    float E = e_post[row];
    return 0.5f * (sums[0] + P * sums[1] + C * sums[2] + D * sums[3]
          + E * (sums[4] + P * sums[5] + C * sums[6] + D * sums[7]));
}

__device__ __forceinline__ void heb_partial4(
    float s[8], float4 xv, float4 actv, float4 av, float4 cv, float4 dv, float4 ev)
{
    float xs[4]  = {xv.x, xv.y, xv.z, xv.w};
    float acs[4] = {actv.x, actv.y, actv.z, actv.w};
    float as[4]  = {av.x, av.y, av.z, av.w};
    float cs[4]  = {cv.x, cv.y, cv.z, cv.w};
    float ds[4]  = {dv.x, dv.y, dv.z, dv.w};
    float es[4]  = {ev.x, ev.y, ev.z, ev.w};
#pragma unroll
    for (int j = 0; j < 4; j++) {
        float x = xs[j], e = es[j];
        float p = as[j] * acs[j];
        float c = cs[j] * acs[j];
        float d = ds[j];
        s[0] += e * p * x;  s[1] += e * x;
        s[2] += e * c * x;  s[3] += e * d * x;
        s[4] += p * x;      s[5] += x;
        s[6] += c * x;      s[7] += d * x;
    }
}

// ---------------------------------------------------------------------------
// Fused GEMV (R8 architecture): cp.async row pipeline NBUF deep, x in
// registers, thread t owns f4-columns {t, t+512, ...}. Per-row shfl reduce;
// no block barrier on the data path.
// PDL_TRIG: signal dependents launchable after our prologue prefetch.
// PDL_WAIT: wait for prior grid's memory (g_x1) before the x staging phase.
// ---------------------------------------------------------------------------
template <int NCOL4, int NROWS_OUT, bool TANH_IN, bool TANH_OUT, int NBUF,
          bool PDL_TRIG, bool PDL_WAIT>
__device__ __forceinline__ void gemv_fused(
    const float* __restrict__ W,
    const float* __restrict__ xin_src,
    const float* __restrict__ act_pre,
    const float* __restrict__ a_pre,
    const float* __restrict__ c_pre,
    const float* __restrict__ d_pre,
    const float* __restrict__ e_pre,
    const float* __restrict__ act_post,
    const float* __restrict__ b_post,
    const float* __restrict__ c_post,
    const float* __restrict__ d_post,
    const float* __restrict__ e_post,
    float* __restrict__ out)
{
    constexpr int F4PT = NCOL4 / BLK;     // float4 per thread per row (2 or 4)

    extern __shared__ float4 dynbuf[];    // NBUF * NCOL4 float4 (96 KB)
    __shared__ float sh[8][16];
    __shared__ float s_sums[8];
    __shared__ float s_heb[32];
    __shared__ float s_part[2][8][16];

    int tid = threadIdx.x;
    int lane = tid & 31;
    int warp = tid >> 5;

    int r_lo = (int)(((long long)blockIdx.x * NROWS_OUT) / NBLK);
    int r_hi = (int)(((long long)(blockIdx.x + 1) * NROWS_OUT) / NBLK);
    int nrows = r_hi - r_lo;

    const float4* Wb = reinterpret_cast<const float4*>(W) + (size_t)r_lo * NCOL4;
    uint32_t sbase = smem_u32(dynbuf);

    // Kick off DRAM immediately: prefetch first NBUF rows (W only — input data,
    // safe before pdl_wait).
#pragma unroll
    for (int r = 0; r < NBUF; r++) {
        if (r < nrows) {
#pragma unroll
            for (int j = 0; j < F4PT; j++) {
                int col = tid + j * BLK;
                cp_async16(sbase + (uint32_t)(r * NCOL4 + col) * 16u,
                           Wb + (size_t)r * NCOL4 + col);
            }
        }
        CP_COMMIT();
    }

    if (PDL_TRIG) pdl_trigger();   // dependents may start launching now
    if (PDL_WAIT) pdl_wait();      // prior grid's writes (g_x1) now visible

    // x into registers (+tanh), Hebbian pre-side sums (overlaps prefetch).
    float4 xr[F4PT];
    {
        float s[8] = {0.f, 0.f, 0.f, 0.f, 0.f, 0.f, 0.f, 0.f};
#pragma unroll
        for (int j = 0; j < F4PT; j++) {
            int i = tid + j * BLK;
            float4 xv = reinterpret_cast<const float4*>(xin_src)[i];
            if (TANH_IN)
                xv = make_float4(tanhf(xv.x), tanhf(xv.y), tanhf(xv.z), tanhf(xv.w));
            xr[j] = xv;
            float4 actv = reinterpret_cast<const float4*>(act_pre)[i];
            float4 av   = reinterpret_cast<const float4*>(a_pre)[i];
            float4 cv   = reinterpret_cast<const float4*>(c_pre)[i];
            float4 dv   = reinterpret_cast<const float4*>(d_pre)[i];
            float4 ev   = reinterpret_cast<const float4*>(e_pre)[i];
            heb_partial4(s, xv, actv, av, cv, dv, ev);
        }
        block_reduce8(s, sh, s_sums);
    }
    __syncthreads();
    if (tid < nrows) {
        s_heb[tid] = heb_row_val(r_lo + tid, act_post, b_post, c_post, d_post,
                                 e_post, s_sums);
    }
    __syncthreads();

    // Rolling state.
    int rdSlot = 0;
    int wrSlot = 0;                               // row NBUF writes slot 0
    const float4* gsrc = Wb + (size_t)NBUF * NCOL4 + tid;

    int par = 0;
    for (int r = 0; r < nrows; r++) {
        CP_WAIT(NBUF - 1);

        const float4* buf = dynbuf + (size_t)rdSlot * NCOL4;
        float4 wv[F4PT];
#pragma unroll
        for (int j = 0; j < F4PT; j++) wv[j] = buf[tid + j * BLK];
        rdSlot = (rdSlot + 1 == NBUF) ? 0 : rdSlot + 1;

        float acc = 0.f;
#pragma unroll
        for (int j = 0; j < F4PT; j++) {
            acc = fmaf(wv[j].x, xr[j].x, acc);
            acc = fmaf(wv[j].y, xr[j].y, acc);
            acc = fmaf(wv[j].z, xr[j].z, acc);
            acc = fmaf(wv[j].w, xr[j].w, acc);
        }
        float p = warp_sum(acc);
        if (lane == 0) s_part[par][r & 7][warp] = p;

        if (r + NBUF < nrows) {
            uint32_t wbase = sbase + (uint32_t)(wrSlot * NCOL4 + tid) * 16u;
#pragma unroll
            for (int j = 0; j < F4PT; j++)
                cp_async16(wbase + (uint32_t)(j * BLK) * 16u, gsrc + j * BLK);
        }
        wrSlot = (wrSlot + 1 == NBUF) ? 0 : wrSlot + 1;
        gsrc += NCOL4;
        CP_COMMIT();

        if ((r & 7) == 7 || r == nrows - 1) {
            __syncthreads();
            if (tid < 256) {
                int rr = (r & ~7) + warp;     // warp = 0..7 here
                if (rr < nrows) {
                    float v = (lane < 16) ? s_part[par][warp][lane] : 0.f;
                    v = warp_sum(v);
                    if (lane == 0) {
                        float y = v + s_heb[rr];
                        out[r_lo + rr] = TANH_OUT ? tanhf(y) : y;
                    }
                }
            }
            par ^= 1;
        }
    }
}

// ---------------------------------------------------------------------------
__global__ void __launch_bounds__(BLK, 2) k_gemv0(
    const float* __restrict__ W0,
    const float* __restrict__ inputs,
    const float* __restrict__ act0,
    const float* __restrict__ a0,
    const float* __restrict__ c0,
    const float* __restrict__ d0,
    const float* __restrict__ e0,
    const float* __restrict__ act1,
    const float* __restrict__ b1,
    const float* __restrict__ c1,
    const float* __restrict__ d1,
    const float* __restrict__ e1)
{
    gemv_fused<N0 / 4, N1, true, true, 6, true, false>(
        W0, inputs, act0, a0, c0, d0, e0,
        act1, b1, c1, d1, e1, g_x1);
}

__global__ void __launch_bounds__(BLK, 2) k_gemv1(
    const float* __restrict__ W1,
    const float* __restrict__ act1,
    const float* __restrict__ a1,
    const float* __restrict__ c1,
    const float* __restrict__ d1,
    const float* __restrict__ e1,
    const float* __restrict__ act2,
    const float* __restrict__ b2,
    const float* __restrict__ c2,
    const float* __restrict__ d2,
    const float* __restrict__ e2,
    float* __restrict__ out)
{
    gemv_fused<N1 / 4, N2, false, false, 3, false, true>(
        W1, g_x1, act1, a1, c1, d1, e1,
        act2, b2, c2, d2, e2, out);
}

// ---------------------------------------------------------------------------
extern "C" void kernel_launch(void* const* d_in, const int* in_sizes, int n_in,
                              void* d_out, int out_size)
{
    const float* inputs = (const float*)d_in[0];
    const float* act0   = (const float*)d_in[1];
    const float* act1   = (const float*)d_in[2];
    const float* act2   = (const float*)d_in[3];
    const float* W0     = (const float*)d_in[4];
    const float* W1     = (const float*)d_in[5];
    const float* a0     = (const float*)d_in[6];
    const float* c0     = (const float*)d_in[7];
    const float* d0     = (const float*)d_in[8];
    const float* e0     = (const float*)d_in[9];
    const float* a1     = (const float*)d_in[10];
    const float* b1     = (const float*)d_in[11];
    const float* c1     = (const float*)d_in[12];
    const float* d1     = (const float*)d_in[13];
    const float* e1     = (const float*)d_in[14];
    const float* b2     = (const float*)d_in[15];
    const float* c2     = (const float*)d_in[16];
    const float* d2     = (const float*)d_in[17];
    const float* e2     = (const float*)d_in[18];
    float* out = (float*)d_out;

    // 6 buffers * 1024 f4 (gemv0) == 3 buffers * 2048 f4 (gemv1) == 96 KB.
    const int SMEM_DYN = 6 * (N0 / 4) * (int)sizeof(float4);
    static bool attr_done = false;
    if (!attr_done) {
        cudaFuncSetAttribute(k_gemv0, cudaFuncAttributeMaxDynamicSharedMemorySize, SMEM_DYN);
        cudaFuncSetAttribute(k_gemv1, cudaFuncAttributeMaxDynamicSharedMemorySize, SMEM_DYN);
        attr_done = true;
    }

    // Primary: normal launch.
    k_gemv0<<<NBLK, BLK, SMEM_DYN>>>(W0, inputs, act0, a0, c0, d0, e0,
                                     act1, b1, c1, d1, e1);

    // Secondary: programmatic dependent launch (overlaps its W1 prefetch with
    // gemv0's tail; pdl_wait() inside orders the g_x1 reads).
    cudaLaunchConfig_t cfg = {};
    cfg.gridDim = dim3(NBLK, 1, 1);
    cfg.blockDim = dim3(BLK, 1, 1);
    cfg.dynamicSmemBytes = (size_t)SMEM_DYN;
    cfg.stream = 0;
    cudaLaunchAttribute attrs[1];
    attrs[0].id = cudaLaunchAttributeProgrammaticStreamSerialization;
    attrs[0].val.programmaticStreamSerializationAllowed = 1;
    cfg.attrs = attrs;
    cfg.numAttrs = 1;
    cudaLaunchKernelEx(&cfg, k_gemv1,
                       W1, act1, a1, c1, d1, e1,
                       act2, b2, c2, d2, e2, out);
}